// round 3
// baseline (speedup 1.0000x reference)
#include <cuda_runtime.h>

// Problem constants
#define Bn  8192
#define Dn  1024
#define Hn  8
#define HDn 128
#define BMn 64          // rows per block
#define KTn 32          // K-tile depth staged in smem
#define NT  512         // threads per block

#define W_BUF   (4 * KTn * HDn)                  // floats per W buffer (4 gates)
#define SMEM_FLOATS (BMn * HDn + 2 * W_BUF)      // h tile + double-buffered W
#define SMEM_BYTES  (SMEM_FLOATS * 4)            // 163840 B

// ---------------------------------------------------------------------------
// all(n == 0) flag
// ---------------------------------------------------------------------------
__device__ int g_any_nonzero;

__global__ void reset_flag_kernel() { g_any_nonzero = 0; }

__global__ void scan_n_kernel(const float4* __restrict__ n4, int count) {
    int any = 0;
    int stride = gridDim.x * blockDim.x;
    for (int v = blockIdx.x * blockDim.x + threadIdx.x; v < count; v += stride) {
        float4 x = n4[v];
        any |= (x.x != 0.0f) | (x.y != 0.0f) | (x.z != 0.0f) | (x.w != 0.0f);
    }
    if (__syncthreads_or(any)) {
        if (threadIdx.x == 0) atomicOr(&g_any_nonzero, 1);
    }
}

// ---------------------------------------------------------------------------
// Helpers
// ---------------------------------------------------------------------------
__device__ __forceinline__ float2 ffma2(float2 a, float2 b, float2 c) {
#if defined(__CUDA_ARCH__) && (__CUDA_ARCH__ >= 1000)
    float2 d;
    asm("fma.rn.f32x2 %0, %1, %2, %3;"
        : "=l"(*reinterpret_cast<unsigned long long*>(&d))
        : "l"(*reinterpret_cast<unsigned long long*>(&a)),
          "l"(*reinterpret_cast<unsigned long long*>(&b)),
          "l"(*reinterpret_cast<unsigned long long*>(&c)));
    return d;
#else
    return make_float2(fmaf(a.x, b.x, c.x), fmaf(a.y, b.y, c.y));
#endif
}

__device__ __forceinline__ void cp16(float* s, const float* g) {
    unsigned sa = (unsigned)__cvta_generic_to_shared(s);
    asm volatile("cp.async.cg.shared.global [%0], [%1], 16;" :: "r"(sa), "l"(g));
}

__device__ __forceinline__ void stage_w(float* dst, const float* w0, const float* w1,
                                        const float* w2, const float* w3,
                                        int tile, int tid) {
    const int off = tile * KTn * HDn;
#pragma unroll
    for (int it = 0; it < (KTn * HDn / 4) / NT; ++it) {   // 2 iterations
        int v4 = (tid + it * NT) * 4;
        cp16(&dst[0 * KTn * HDn + v4], &w0[off + v4]);
        cp16(&dst[1 * KTn * HDn + v4], &w1[off + v4]);
        cp16(&dst[2 * KTn * HDn + v4], &w2[off + v4]);
        cp16(&dst[3 * KTn * HDn + v4], &w3[off + v4]);
    }
}

// sLSTM pointwise cell math (numerically safe, intrinsic-only so behavior is
// independent of fast-math flags; explicit exp-form tanh for accuracy)
__device__ __forceinline__ void cell_compute(
    float ipre, float fpre, float zpre, float opre,
    float c, float n, float m, bool allzero,
    float& cn, float& nn, float& mn, float& hn)
{
    float og = __fdividef(1.0f, 1.0f + __expf(-opre));                 // sigmoid(o)
    float lf = fminf(fpre, 0.0f) - __logf(1.0f + __expf(-fabsf(fpre))); // log(sigmoid(f))
    float a  = lf + m;
    mn = allzero ? ipre : fmaxf(a, ipre);
    float ip = fminf(__expf(ipre - mn), 1.0f);
    float fp = fminf(__expf(a - mn), 1.0f);
    float e2 = __expf(2.0f * zpre);
    float tz = 1.0f - __fdividef(2.0f, e2 + 1.0f);                     // tanh(z)
    cn = fp * c + ip * tz;
    nn = fp * n + ip;
    hn = og * __fdividef(cn, fmaxf(nn, 1e-6f));
}

// ---------------------------------------------------------------------------
// Fused sLSTM kernel: block = 64 rows x 1 head (128 cols), all 4 gates
// ---------------------------------------------------------------------------
__global__ void __launch_bounds__(NT, 1) slstm_kernel(
    const float* __restrict__ gi, const float* __restrict__ gf,
    const float* __restrict__ gz, const float* __restrict__ go,
    const float* __restrict__ gc, const float* __restrict__ gn,
    const float* __restrict__ gm, const float* __restrict__ gh,
    const float* __restrict__ Wi, const float* __restrict__ Wf,
    const float* __restrict__ Wz, const float* __restrict__ Wo,
    const float* __restrict__ bi, const float* __restrict__ bf,
    const float* __restrict__ bz, const float* __restrict__ bo,
    float* __restrict__ out)
{
    extern __shared__ float smem[];
    float* h_s = smem;                 // BMn * HDn
    float* Ws  = smem + BMn * HDn;     // 2 * W_BUF

    const int tid  = threadIdx.x;
    const int head = blockIdx.y;
    const int row0 = blockIdx.x * BMn;

    const float* W0p = Wi + head * HDn * HDn;
    const float* W1p = Wf + head * HDn * HDn;
    const float* W2p = Wz + head * HDn * HDn;
    const float* W3p = Wo + head * HDn * HDn;

    // Stage h tile (64x128) + W tile 0 as cp.async group 0
#pragma unroll
    for (int it = 0; it < (BMn * HDn / 4) / NT; ++it) {   // 4 iterations
        int v = tid + it * NT;
        int r = v >> 5;        // 32 float4 per row
        int s = (v & 31) * 4;
        cp16(&h_s[r * HDn + s], &gh[(size_t)(row0 + r) * Dn + head * HDn + s]);
    }
    stage_w(Ws, W0p, W1p, W2p, W3p, 0, tid);
    asm volatile("cp.async.commit_group;");

    const int cp = tid & 63;       // column pair index 0..63
    const int rg = tid >> 6;       // row group 0..7 (8 rows each)
    const int c0 = cp << 1;

    float2 accI[8], accF[8], accZ[8], accO[8];
#pragma unroll
    for (int j = 0; j < 8; ++j) {
        accI[j] = make_float2(0.f, 0.f);
        accF[j] = make_float2(0.f, 0.f);
        accZ[j] = make_float2(0.f, 0.f);
        accO[j] = make_float2(0.f, 0.f);
    }

#pragma unroll 1
    for (int t = 0; t < HDn / KTn; ++t) {      // 4 K-tiles
        if (t < HDn / KTn - 1) {
            stage_w(Ws + ((t + 1) & 1) * W_BUF, W0p, W1p, W2p, W3p, t + 1, tid);
            asm volatile("cp.async.commit_group;");
            asm volatile("cp.async.wait_group 1;");
        } else {
            asm volatile("cp.async.wait_group 0;");
        }
        __syncthreads();

        const float* Wt   = Ws + (t & 1) * W_BUF;
        const float* hrow = h_s + (rg * 8) * HDn + t * KTn;

#pragma unroll 2
        for (int k2 = 0; k2 < KTn; k2 += 2) {
            float2 hv[8];
#pragma unroll
            for (int j = 0; j < 8; ++j)
                hv[j] = *(const float2*)&hrow[j * HDn + k2];
#pragma unroll
            for (int u = 0; u < 2; ++u) {
                const int k = k2 + u;
                float2 w_i = *(const float2*)&Wt[0 * KTn * HDn + k * HDn + c0];
                float2 w_f = *(const float2*)&Wt[1 * KTn * HDn + k * HDn + c0];
                float2 w_z = *(const float2*)&Wt[2 * KTn * HDn + k * HDn + c0];
                float2 w_o = *(const float2*)&Wt[3 * KTn * HDn + k * HDn + c0];
#pragma unroll
                for (int j = 0; j < 8; ++j) {
                    float hs = (u == 0) ? hv[j].x : hv[j].y;
                    float2 hb = make_float2(hs, hs);
                    accI[j] = ffma2(hb, w_i, accI[j]);
                    accF[j] = ffma2(hb, w_f, accF[j]);
                    accZ[j] = ffma2(hb, w_z, accZ[j]);
                    accO[j] = ffma2(hb, w_o, accO[j]);
                }
            }
        }
        __syncthreads();
    }

    // ---------------- epilogue: pointwise sLSTM cell ----------------
    const int colg = head * HDn + c0;
    const float2 b_i = *(const float2*)&bi[colg];
    const float2 b_f = *(const float2*)&bf[colg];
    const float2 b_z = *(const float2*)&bz[colg];
    const float2 b_o = *(const float2*)&bo[colg];
    const bool allz = (g_any_nonzero == 0);

    const size_t BD = (size_t)Bn * Dn;
    float* out_c = out;
    float* out_n = out + BD;
    float* out_m = out + 2 * BD;
    float* out_h = out + 3 * BD;

#pragma unroll
    for (int j = 0; j < 8; ++j) {
        const int row = row0 + rg * 8 + j;
        const size_t idx = (size_t)row * Dn + colg;
        float2 vi = *(const float2*)&gi[idx];
        float2 vf = *(const float2*)&gf[idx];
        float2 vz = *(const float2*)&gz[idx];
        float2 vo = *(const float2*)&go[idx];
        float2 vc = *(const float2*)&gc[idx];
        float2 vn = *(const float2*)&gn[idx];
        float2 vm = *(const float2*)&gm[idx];

        float2 rc, rn, rm, rh;
        cell_compute(vi.x + accI[j].x + b_i.x, vf.x + accF[j].x + b_f.x,
                     vz.x + accZ[j].x + b_z.x, vo.x + accO[j].x + b_o.x,
                     vc.x, vn.x, vm.x, allz, rc.x, rn.x, rm.x, rh.x);
        cell_compute(vi.y + accI[j].y + b_i.y, vf.y + accF[j].y + b_f.y,
                     vz.y + accZ[j].y + b_z.y, vo.y + accO[j].y + b_o.y,
                     vc.y, vn.y, vm.y, allz, rc.y, rn.y, rm.y, rh.y);

        *(float2*)&out_c[idx] = rc;
        *(float2*)&out_n[idx] = rn;
        *(float2*)&out_m[idx] = rm;
        *(float2*)&out_h[idx] = rh;
    }
}

// ---------------------------------------------------------------------------
// Launch
// ---------------------------------------------------------------------------
extern "C" void kernel_launch(void* const* d_in, const int* in_sizes, int n_in,
                              void* d_out, int out_size) {
    // metadata order follows setup_inputs dict insertion order:
    //   i, f, z, o, c, m, h, n, Wi, Wf, Wz, Wo, bi, bf, bz, bo
    const float* gi = (const float*)d_in[0];
    const float* gf = (const float*)d_in[1];
    const float* gz = (const float*)d_in[2];
    const float* go = (const float*)d_in[3];
    const float* gc = (const float*)d_in[4];
    const float* gm = (const float*)d_in[5];
    const float* gh = (const float*)d_in[6];
    const float* gn = (const float*)d_in[7];
    const float* Wi = (const float*)d_in[8];
    const float* Wf = (const float*)d_in[9];
    const float* Wz = (const float*)d_in[10];
    const float* Wo = (const float*)d_in[11];
    const float* bi = (const float*)d_in[12];
    const float* bf = (const float*)d_in[13];
    const float* bz = (const float*)d_in[14];
    const float* bo = (const float*)d_in[15];
    float* out = (float*)d_out;

    cudaFuncSetAttribute(slstm_kernel, cudaFuncAttributeMaxDynamicSharedMemorySize,
                         SMEM_BYTES);

    reset_flag_kernel<<<1, 1>>>();
    scan_n_kernel<<<2048, 256>>>((const float4*)gn, (Bn * Dn) / 4);

    dim3 grid(Bn / BMn, Hn);
    slstm_kernel<<<grid, NT, SMEM_BYTES>>>(gi, gf, gz, go, gc, gn, gm, gh,
                                           Wi, Wf, Wz, Wo, bi, bf, bz, bo, out);
}

// round 6
// speedup vs baseline: 1.4677x; 1.4677x over previous
#include <cuda_runtime.h>
#include <cuda_bf16.h>
#include <cstdint>

// ---------------------------------------------------------------------------
// Problem constants
// ---------------------------------------------------------------------------
#define Bn  8192
#define Dn  1024
#define Hn  8
#define HDn 128
#define BM  64             // rows per CTA
#define NT  512            // threads per CTA (16 warps: 4 row-groups x 4 col-groups)

// A smem tile: 64 rows x 136 bf16 (128 data + 4 pad elems -> 272B rows, bank-safe)
#define A_LDE 136
#define A_TILE_BYTES (BM * A_LDE * 2)          // 17408
#define OFF_AHI 0
#define OFF_ALO A_TILE_BYTES
#define SMEM_BYTES (2 * A_TILE_BYTES)          // 34816

// ---------------------------------------------------------------------------
// Device scratch: W pre-packed in mma.m16n8k16 B-fragment layout (bf16 hi/lo)
// Layout (uint32 units): [head][gate][kstep(8)][ntile(16)][lane(32)][reg(2)]
//   reg uint32 = pack( W[k, n], W[k+1, n] ),
//   k = kstep*16 + reg*8 + (lane&3)*2,  n = ntile*8 + (lane>>2)
// ---------------------------------------------------------------------------
#define WFRAG_PER_HEAD (4 * 8 * 16 * 32 * 2)   // 32768 uint32
__device__ uint32_t g_Bhi[Hn * WFRAG_PER_HEAD];
__device__ uint32_t g_Blo[Hn * WFRAG_PER_HEAD];
__device__ int g_any_nonzero;

// ---------------------------------------------------------------------------
// Helpers
// ---------------------------------------------------------------------------
__device__ __forceinline__ uint32_t smem_u32(const void* p) {
    uint32_t a;
    asm("{ .reg .u64 t; cvta.to.shared.u64 t, %1; cvt.u32.u64 %0, t; }"
        : "=r"(a) : "l"(p));
    return a;
}

__device__ __forceinline__ void ldsm4(uint32_t* r, uint32_t addr) {
    asm volatile("ldmatrix.sync.aligned.m8n8.x4.shared.b16 {%0,%1,%2,%3}, [%4];"
                 : "=r"(r[0]), "=r"(r[1]), "=r"(r[2]), "=r"(r[3]) : "r"(addr));
}

__device__ __forceinline__ void mma_bf16(float* c, const uint32_t* a, uint32_t b0, uint32_t b1) {
    asm volatile("mma.sync.aligned.m16n8k16.row.col.f32.bf16.bf16.f32 "
                 "{%0,%1,%2,%3}, {%4,%5,%6,%7}, {%8,%9}, {%0,%1,%2,%3};"
                 : "+f"(c[0]), "+f"(c[1]), "+f"(c[2]), "+f"(c[3])
                 : "r"(a[0]), "r"(a[1]), "r"(a[2]), "r"(a[3]), "r"(b0), "r"(b1));
}

__device__ __forceinline__ uint32_t pack_bf16(float a, float b) {
    return (uint32_t)__bfloat16_as_ushort(__float2bfloat16_rn(a)) |
           ((uint32_t)__bfloat16_as_ushort(__float2bfloat16_rn(b)) << 16);
}

// ---------------------------------------------------------------------------
// all(n == 0) flag
// ---------------------------------------------------------------------------
__global__ void reset_flag_kernel() { g_any_nonzero = 0; }

__global__ void scan_n_kernel(const float4* __restrict__ n4, int count) {
    int any = 0;
    int stride = gridDim.x * blockDim.x;
    for (int v = blockIdx.x * blockDim.x + threadIdx.x; v < count; v += stride) {
        float4 x = n4[v];
        any |= (x.x != 0.0f) | (x.y != 0.0f) | (x.z != 0.0f) | (x.w != 0.0f);
    }
    if (__syncthreads_or(any)) {
        if (threadIdx.x == 0) atomicOr(&g_any_nonzero, 1);
    }
}

// ---------------------------------------------------------------------------
// W -> B-fragment converter (one thread per packed uint32)
// ---------------------------------------------------------------------------
__global__ void convert_w_frag(const float* __restrict__ Wi, const float* __restrict__ Wf,
                               const float* __restrict__ Wz, const float* __restrict__ Wo) {
    int id = blockIdx.x * blockDim.x + threadIdx.x;     // 262144 total
    int r    = id & 1;
    int lane = (id >> 1) & 31;
    int nt   = (id >> 6) & 15;
    int ks   = (id >> 10) & 7;
    int g    = (id >> 13) & 3;
    int h    = id >> 15;
    int k = ks * 16 + r * 8 + (lane & 3) * 2;
    int n = nt * 8 + (lane >> 2);
    const float* W = (g == 0) ? Wi : (g == 1) ? Wf : (g == 2) ? Wz : Wo;
    float x0 = W[h * 16384 + k * 128 + n];
    float x1 = W[h * 16384 + (k + 1) * 128 + n];
    float h0 = __bfloat162float(__float2bfloat16_rn(x0));
    float h1 = __bfloat162float(__float2bfloat16_rn(x1));
    g_Bhi[id] = pack_bf16(x0, x1);
    g_Blo[id] = pack_bf16(x0 - h0, x1 - h1);
}

// ---------------------------------------------------------------------------
// sLSTM pointwise cell (validated in R3: rel_err 1e-7)
// ---------------------------------------------------------------------------
__device__ __forceinline__ void cell_compute(
    float ipre, float fpre, float zpre, float opre,
    float c, float n, float m, bool allzero,
    float& cn, float& nn, float& mn, float& hn)
{
    float og = __fdividef(1.0f, 1.0f + __expf(-opre));
    float lf = fminf(fpre, 0.0f) - __logf(1.0f + __expf(-fabsf(fpre)));
    float a  = lf + m;
    mn = allzero ? ipre : fmaxf(a, ipre);
    float ip = fminf(__expf(ipre - mn), 1.0f);
    float fp = fminf(__expf(a - mn), 1.0f);
    float e2 = __expf(2.0f * zpre);
    float tz = 1.0f - __fdividef(2.0f, e2 + 1.0f);
    cn = fp * c + ip * tz;
    nn = fp * n + ip;
    hn = og * __fdividef(cn, fmaxf(nn, 1e-6f));
}

// ---------------------------------------------------------------------------
// Main kernel: CTA = 64 rows x 1 head; mma.sync bf16x3 + fused epilogue
// Warp w: wm = w&3 -> rows [16*wm, 16*wm+16); wc = w>>2 -> cols [32*wc, 32*wc+32)
// Each warp computes its 16x32 patch for ALL 4 gates.
// ---------------------------------------------------------------------------
__global__ void __launch_bounds__(NT) slstm_mma_kernel(
    const float* __restrict__ gi, const float* __restrict__ gf,
    const float* __restrict__ gz, const float* __restrict__ go,
    const float* __restrict__ gc, const float* __restrict__ gn,
    const float* __restrict__ gm, const float* __restrict__ gh,
    const float* __restrict__ bi, const float* __restrict__ bf,
    const float* __restrict__ bz, const float* __restrict__ bo,
    float* __restrict__ out)
{
    extern __shared__ char smem[];
    const uint32_t sb = smem_u32(smem);
    const int tid  = threadIdx.x;
    const int w    = tid >> 5;
    const int lane = tid & 31;
    const int wm   = w & 3;
    const int wc   = w >> 2;
    const int head = blockIdx.y;
    const int row0 = blockIdx.x * BM;

    // ---- load h tile (64x128 f32), split hi/lo bf16 into smem ----
#pragma unroll
    for (int it = 0; it < (BM * HDn / 4) / NT; ++it) {   // 4 iters
        int v = tid + it * NT;
        int r = v >> 5;
        int kq = (v & 31) * 4;
        float4 x = *(const float4*)&gh[(size_t)(row0 + r) * Dn + head * HDn + kq];
        float h0 = __bfloat162float(__float2bfloat16_rn(x.x));
        float h1 = __bfloat162float(__float2bfloat16_rn(x.y));
        float h2 = __bfloat162float(__float2bfloat16_rn(x.z));
        float h3 = __bfloat162float(__float2bfloat16_rn(x.w));
        uint2 hi2 = make_uint2(pack_bf16(x.x, x.y), pack_bf16(x.z, x.w));
        uint2 lo2 = make_uint2(pack_bf16(x.x - h0, x.y - h1), pack_bf16(x.z - h2, x.w - h3));
        uint32_t boff = (uint32_t)(r * A_LDE + kq) * 2;
        *(uint2*)(smem + OFF_AHI + boff) = hi2;
        *(uint2*)(smem + OFF_ALO + boff) = lo2;
    }
    __syncthreads();

    // ldmatrix lane address component (canonical row-major A-frag)
    const uint32_t lm_lane_off =
        (uint32_t)((wm * 16 + (lane & 15)) * A_LDE * 2 + (lane >> 4) * 16);

    float acc[4][4][4];                                  // [gate][ntile][creg]
#pragma unroll
    for (int g = 0; g < 4; ++g)
#pragma unroll
        for (int t = 0; t < 4; ++t)
#pragma unroll
            for (int q = 0; q < 4; ++q) acc[g][t][q] = 0.0f;

    const uint32_t* Bh = g_Bhi + (size_t)head * WFRAG_PER_HEAD;
    const uint32_t* Bl = g_Blo + (size_t)head * WFRAG_PER_HEAD;

    // 3 passes: (A_hi,B_hi), (A_lo,B_hi), (A_hi,B_lo)
#pragma unroll 1
    for (int p = 0; p < 3; ++p) {
        const uint32_t a_base = sb + ((p == 1) ? OFF_ALO : OFF_AHI) + lm_lane_off;
        const uint32_t* Bp = (p == 2) ? Bl : Bh;
#pragma unroll
        for (int ks = 0; ks < 8; ++ks) {
            uint32_t a[4];
            ldsm4(a, a_base + ks * 32);                  // 16 bf16 cols = 32B
#pragma unroll
            for (int g = 0; g < 4; ++g) {
#pragma unroll
                for (int t = 0; t < 4; ++t) {
                    const uint32_t* bp =
                        Bp + (((g * 8 + ks) * 16 + (wc * 4 + t)) * 32 + lane) * 2;
                    uint2 b = *(const uint2*)bp;
                    mma_bf16(acc[g][t], a, b.x, b.y);
                }
            }
        }
    }

    // ---- fused epilogue ----
    const bool allz = (g_any_nonzero == 0);
    const size_t BD = (size_t)Bn * Dn;
    float* out_c = out;
    float* out_n = out + BD;
    float* out_m = out + 2 * BD;
    float* out_h = out + 3 * BD;

    const int r0 = row0 + wm * 16 + (lane >> 2);

#pragma unroll
    for (int rr = 0; rr < 2; ++rr) {
        const int row = r0 + rr * 8;
#pragma unroll
        for (int t = 0; t < 4; ++t) {
            const int col = head * HDn + wc * 32 + t * 8 + (lane & 3) * 2;
            const size_t idx = (size_t)row * Dn + col;
            float2 vi = *(const float2*)&gi[idx];
            float2 vf = *(const float2*)&gf[idx];
            float2 vz = *(const float2*)&gz[idx];
            float2 vo = *(const float2*)&go[idx];
            float2 vc = *(const float2*)&gc[idx];
            float2 vn = *(const float2*)&gn[idx];
            float2 vm = *(const float2*)&gm[idx];
            float2 B_i = *(const float2*)&bi[col];
            float2 B_f = *(const float2*)&bf[col];
            float2 B_z = *(const float2*)&bz[col];
            float2 B_o = *(const float2*)&bo[col];

            const int q0 = rr * 2;                       // c-frag: {c0,c1} rows m, {c2,c3} rows m+8
            float2 rc, rn_, rm_, rh;
            cell_compute(vi.x + acc[0][t][q0]     + B_i.x,
                         vf.x + acc[1][t][q0]     + B_f.x,
                         vz.x + acc[2][t][q0]     + B_z.x,
                         vo.x + acc[3][t][q0]     + B_o.x,
                         vc.x, vn.x, vm.x, allz, rc.x, rn_.x, rm_.x, rh.x);
            cell_compute(vi.y + acc[0][t][q0 + 1] + B_i.y,
                         vf.y + acc[1][t][q0 + 1] + B_f.y,
                         vz.y + acc[2][t][q0 + 1] + B_z.y,
                         vo.y + acc[3][t][q0 + 1] + B_o.y,
                         vc.y, vn.y, vm.y, allz, rc.y, rn_.y, rm_.y, rh.y);

            *(float2*)&out_c[idx] = rc;
            *(float2*)&out_n[idx] = rn_;
            *(float2*)&out_m[idx] = rm_;
            *(float2*)&out_h[idx] = rh;
        }
    }
}

// ---------------------------------------------------------------------------
// Launch
// ---------------------------------------------------------------------------
extern "C" void kernel_launch(void* const* d_in, const int* in_sizes, int n_in,
                              void* d_out, int out_size) {
    // metadata order (dict insertion): i, f, z, o, c, m, h, n, Wi, Wf, Wz, Wo, bi, bf, bz, bo
    const float* gi = (const float*)d_in[0];
    const float* gf = (const float*)d_in[1];
    const float* gz = (const float*)d_in[2];
    const float* go = (const float*)d_in[3];
    const float* gc = (const float*)d_in[4];
    const float* gm = (const float*)d_in[5];
    const float* gh = (const float*)d_in[6];
    const float* gn = (const float*)d_in[7];
    const float* Wi = (const float*)d_in[8];
    const float* Wf = (const float*)d_in[9];
    const float* Wz = (const float*)d_in[10];
    const float* Wo = (const float*)d_in[11];
    const float* bi = (const float*)d_in[12];
    const float* bf = (const float*)d_in[13];
    const float* bz = (const float*)d_in[14];
    const float* bo = (const float*)d_in[15];
    float* out = (float*)d_out;

    cudaFuncSetAttribute(slstm_mma_kernel, cudaFuncAttributeMaxDynamicSharedMemorySize,
                         SMEM_BYTES);

    reset_flag_kernel<<<1, 1>>>();
    scan_n_kernel<<<2048, 256>>>((const float4*)gn, (Bn * Dn) / 4);
    convert_w_frag<<<1024, 256>>>(Wi, Wf, Wz, Wo);

    dim3 grid(Bn / BM, Hn);
    slstm_mma_kernel<<<grid, NT, SMEM_BYTES>>>(gi, gf, gz, go, gc, gn, gm, gh,
                                               bi, bf, bz, bo, out);
}